// round 1
// baseline (speedup 1.0000x reference)
#include <cuda_runtime.h>
#include <math.h>

// Problem constants
#define MFFT 8192      // complex FFT size (packed real of N=16384)
#define MH   4096      // MFFT/2
#define LOGM 13
#define HDIM 512
#define BDIM 8
#define LDIM 8192

// Device scratch (static __device__ arrays: allowed; no runtime allocation)
__device__ float2 g_Kf[HDIM * 8193];                 // rfft(k, 16384) per h, natural order
__device__ float  g_G[(size_t)BDIM * HDIM * LDIM];   // gelu(conv + skip), (B,H,L)

__device__ __forceinline__ float2 cmulf2(float2 a, float2 b) {
    return make_float2(a.x * b.x - a.y * b.y, a.x * b.y + a.y * b.x);
}
__device__ __forceinline__ float2 caddf2(float2 a, float2 b) { return make_float2(a.x + b.x, a.y + b.y); }
__device__ __forceinline__ float2 csubf2(float2 a, float2 b) { return make_float2(a.x - b.x, a.y - b.y); }
__device__ __forceinline__ float2 conjf2(float2 a) { return make_float2(a.x, -a.y); }
__device__ __forceinline__ int rev13(int k) { return (int)(__brev((unsigned)k) >> 19); }

__device__ __forceinline__ void fill_tw(float2* TW, int tid, int nthreads) {
    for (int t = tid; t < MH; t += nthreads) {
        float ang = -6.283185307179586f * ((float)t / 8192.0f);
        float s, c;
        sincosf(ang, &s, &c);
        TW[t] = make_float2(c, s);
    }
}

// In-place radix-2 DIF: natural input -> bit-reversed output.
__device__ void fft_forward(float2* A, const float2* TW, int tid, int nthreads) {
    for (int s = 0; s < LOGM; s++) {
        int shift = (LOGM - 1) - s;   // log2(d)
        int d = 1 << shift;
        __syncthreads();
        for (int j = tid; j < MH; j += nthreads) {
            int pos = j & (d - 1);
            int i0 = ((j >> shift) << (shift + 1)) + pos;
            int i1 = i0 + d;
            float2 a = A[i0], b = A[i1];
            A[i0] = caddf2(a, b);
            float2 t = csubf2(a, b);
            float2 w = TW[pos << s];
            A[i1] = cmulf2(t, w);
        }
    }
    __syncthreads();
}

// In-place radix-2 DIT with conjugate twiddles: bit-reversed input -> natural output.
// Unnormalized (caller scales by 1/MFFT).
__device__ void fft_inverse(float2* A, const float2* TW, int tid, int nthreads) {
    for (int s = 0; s < LOGM; s++) {
        int d = 1 << s;
        __syncthreads();
        for (int j = tid; j < MH; j += nthreads) {
            int pos = j & (d - 1);
            int i0 = ((j >> s) << (s + 1)) + pos;
            int i1 = i0 + d;
            float2 w = TW[pos << ((LOGM - 1) - s)];
            w.y = -w.y;
            float2 t = cmulf2(A[i1], w);
            float2 a = A[i0];
            A[i0] = caddf2(a, t);
            A[i1] = csubf2(a, t);
        }
    }
    __syncthreads();
}

// Kernel A: Kf[h] = rfft(k[h], 16384), natural order, 8193 bins.
extern "C" __global__ void __launch_bounds__(512) kf_kernel(const float* __restrict__ kin) {
    extern __shared__ float2 sh[];
    float2* A  = sh;
    float2* TW = sh + MFFT;
    int tid = threadIdx.x;
    int h = blockIdx.x;
    const float2* kp = (const float2*)(kin + (size_t)h * LDIM);
    fill_tw(TW, tid, 512);
    for (int j = tid; j < MH; j += 512) {
        A[j] = kp[j];                       // pack: z[j] = x[2j] + i x[2j+1]
        A[j + MH] = make_float2(0.f, 0.f);  // zero padding half
    }
    fft_forward(A, TW, tid, 512);
    float2* outp = g_Kf + (size_t)h * 8193;
    for (int k = tid; k < MH; k += 512) {
        if (k == 0) {
            float2 Z0 = A[0];
            outp[0]    = make_float2(Z0.x + Z0.y, 0.f);
            outp[8192] = make_float2(Z0.x - Z0.y, 0.f);
            outp[4096] = conjf2(A[1]);      // rev13(4096)==1; X[M/2] = conj(Z[M/2])
        } else {
            float2 Zk = A[rev13(k)];
            float2 Zm = A[rev13(MFFT - k)];
            float2 cZm = conjf2(Zm);
            float2 E  = make_float2(0.5f * (Zk.x + cZm.x), 0.5f * (Zk.y + cZm.y));
            float2 Dd = csubf2(Zk, cZm);
            float2 O  = make_float2(0.5f * Dd.y, -0.5f * Dd.x);     // -i*(Zk-conj Zm)/2
            float ang = (-3.14159265358979323846f / 8192.0f) * (float)k;  // W_N^k, N=16384
            float sn, cs; sincosf(ang, &sn, &cs);
            float2 W = make_float2(cs, sn);
            float2 WO = cmulf2(W, O);
            outp[k]        = caddf2(E, WO);          // X[k]   = E + W*O
            outp[MFFT - k] = conjf2(csubf2(E, WO));  // X[M-k] = conj(E - W*O)
        }
    }
}

// Kernel B: per (b,h): y = irfft(rfft(u)*Kf)[:L] + D[h]*u ; g = gelu_exact(y) -> g_G
extern "C" __global__ void __launch_bounds__(512) conv_kernel(
    const float* __restrict__ u, const float* __restrict__ Dv) {
    extern __shared__ float2 sh[];
    float2* A  = sh;
    float2* TW = sh + MFFT;
    int tid = threadIdx.x;
    int b = blockIdx.x & (BDIM - 1);
    int h = blockIdx.x >> 3;   // b fastest -> 8 blocks share Kf[h] in L2 per wave
    const float2* up = (const float2*)(u + ((size_t)b * HDIM + h) * LDIM);
    fill_tw(TW, tid, 512);
    for (int j = tid; j < MH; j += 512) {
        A[j] = up[j];
        A[j + MH] = make_float2(0.f, 0.f);
    }
    fft_forward(A, TW, tid, 512);

    const float2* Kf = g_Kf + (size_t)h * 8193;
    // unpack -> multiply by Kf -> repack, all in bit-reversed addressing (pairs disjoint)
    for (int k = tid; k < MH; k += 512) {
        if (k == 0) {
            float2 Z0 = A[0];
            float X0 = Z0.x + Z0.y;
            float XM = Z0.x - Z0.y;
            float2 K0 = Kf[0], KM = Kf[8192];
            float2 Y0 = make_float2(X0 * K0.x, X0 * K0.y);
            float2 YM = make_float2(XM * KM.x, XM * KM.y);
            float2 cYM = conjf2(YM);
            float2 Ep = make_float2(0.5f * (Y0.x + cYM.x), 0.5f * (Y0.y + cYM.y));
            float2 Op = make_float2(0.5f * (Y0.x - cYM.x), 0.5f * (Y0.y - cYM.y));
            A[0] = make_float2(Ep.x - Op.y, Ep.y + Op.x);   // Z'[0] = Ep + i*Op
            float2 Zq = A[1];                                // Z[M/2] (bit-rev index 1)
            float2 Yq = cmulf2(conjf2(Zq), Kf[4096]);
            A[1] = conjf2(Yq);                               // Z'[M/2] = conj(Y[M/2])
        } else {
            int rk = rev13(k), rm = rev13(MFFT - k);
            float2 Zk = A[rk], Zm = A[rm];
            float2 cZm = conjf2(Zm);
            float2 E  = make_float2(0.5f * (Zk.x + cZm.x), 0.5f * (Zk.y + cZm.y));
            float2 Dd = csubf2(Zk, cZm);
            float2 O  = make_float2(0.5f * Dd.y, -0.5f * Dd.x);
            float ang = (-3.14159265358979323846f / 8192.0f) * (float)k;
            float sn, cs; sincosf(ang, &sn, &cs);
            float2 W = make_float2(cs, sn);
            float2 WO = cmulf2(W, O);
            float2 Xk = caddf2(E, WO);
            float2 Xm = conjf2(csubf2(E, WO));
            float2 Yk = cmulf2(Xk, Kf[k]);
            float2 Ym = cmulf2(Xm, Kf[MFFT - k]);
            float2 cYm = conjf2(Ym);
            float2 Ep = make_float2(0.5f * (Yk.x + cYm.x), 0.5f * (Yk.y + cYm.y));
            float2 P  = make_float2(0.5f * (Yk.x - cYm.x), 0.5f * (Yk.y - cYm.y));
            float2 Op = cmulf2(conjf2(W), P);                // O' = W^{-k} * P
            A[rk] = make_float2(Ep.x - Op.y, Ep.y + Op.x);   // Z'[k]   = Ep + i*Op
            A[rm] = make_float2(Ep.x + Op.y, Op.x - Ep.y);   // Z'[M-k] = conj(Ep - i*Op)
        }
    }
    fft_inverse(A, TW, tid, 512);   // leading internal __syncthreads covers the writes above

    float Dh = Dv[h];
    float2* gp = (float2*)(g_G + ((size_t)b * HDIM + h) * LDIM);
    const float inv = 1.0f / (float)MFFT;
    for (int j = tid; j < MH; j += 512) {
        float2 z = A[j];
        float2 uu = up[j];
        float y0 = z.x * inv + Dh * uu.x;
        float y1 = z.y * inv + Dh * uu.y;
        float g0 = 0.5f * y0 * (1.0f + erff(y0 * 0.70710678118654752440f));
        float g1 = 0.5f * y1 * (1.0f + erff(y1 * 0.70710678118654752440f));
        gp[j] = make_float2(g0, g1);
    }
}

// Kernel C: out[b,o,l] = sum_h W[o,h] * g_G[b,h,l] + bias[o]   (fp32 SGEMM 512x512xB*L)
#define GBM 128
#define GBN 128
#define GBK 8
extern "C" __global__ void __launch_bounds__(256) gemm_kernel(
    const float* __restrict__ Wm, const float* __restrict__ bias, float* __restrict__ outp) {
    __shared__ float As[GBK][GBM + 4];
    __shared__ float Bs[GBK][GBN];
    int t = threadIdx.x;
    int b = blockIdx.z;
    int o0 = blockIdx.y * GBM;
    int l0 = blockIdx.x * GBN;
    const float* Gb = g_G + (size_t)b * HDIM * LDIM;
    int tx = t & 15, ty = t >> 4;
    int arow = t >> 1, acol = (t & 1) * 4;
    int brow = t >> 5, bcol = (t & 31) * 4;

    float acc[8][8];
#pragma unroll
    for (int i = 0; i < 8; i++)
#pragma unroll
        for (int j = 0; j < 8; j++) acc[i][j] = 0.f;

    const float* wptr = Wm + (size_t)(o0 + arow) * HDIM + acol;
    const float* gptr = Gb + (size_t)brow * LDIM + l0 + bcol;

    for (int k0 = 0; k0 < HDIM; k0 += GBK) {
        float4 av = *(const float4*)(wptr + k0);
        float4 bv = *(const float4*)(gptr + (size_t)k0 * LDIM);
        __syncthreads();
        As[acol + 0][arow] = av.x;
        As[acol + 1][arow] = av.y;
        As[acol + 2][arow] = av.z;
        As[acol + 3][arow] = av.w;
        *(float4*)&Bs[brow][bcol] = bv;
        __syncthreads();
#pragma unroll
        for (int kk = 0; kk < GBK; kk++) {
            float a[8], bb[8];
            *(float4*)(a)      = *(const float4*)&As[kk][ty * 8];
            *(float4*)(a + 4)  = *(const float4*)&As[kk][ty * 8 + 4];
            *(float4*)(bb)     = *(const float4*)&Bs[kk][tx * 8];
            *(float4*)(bb + 4) = *(const float4*)&Bs[kk][tx * 8 + 4];
#pragma unroll
            for (int i = 0; i < 8; i++)
#pragma unroll
                for (int j = 0; j < 8; j++) acc[i][j] = fmaf(a[i], bb[j], acc[i][j]);
        }
    }

    float* op = outp + ((size_t)b * HDIM + o0 + ty * 8) * LDIM + l0 + tx * 8;
#pragma unroll
    for (int i = 0; i < 8; i++) {
        float bs = bias[o0 + ty * 8 + i];
        float4 v0 = make_float4(acc[i][0] + bs, acc[i][1] + bs, acc[i][2] + bs, acc[i][3] + bs);
        float4 v1 = make_float4(acc[i][4] + bs, acc[i][5] + bs, acc[i][6] + bs, acc[i][7] + bs);
        *(float4*)(op + (size_t)i * LDIM)     = v0;
        *(float4*)(op + (size_t)i * LDIM + 4) = v1;
    }
}

extern "C" void kernel_launch(void* const* d_in, const int* in_sizes, int n_in,
                              void* d_out, int out_size) {
    const float* u    = (const float*)d_in[0];   // (8,512,8192)
    const float* kin  = (const float*)d_in[1];   // (1,512,8192)
    const float* Dv   = (const float*)d_in[2];   // (1,512)
    const float* Wm   = (const float*)d_in[3];   // (512,512)
    const float* bias = (const float*)d_in[4];   // (512,)
    float* outp = (float*)d_out;                 // (8,512,8192)

    size_t smem = (size_t)(MFFT + MH) * sizeof(float2);  // 96 KB
    cudaFuncSetAttribute(kf_kernel,   cudaFuncAttributeMaxDynamicSharedMemorySize, (int)smem);
    cudaFuncSetAttribute(conv_kernel, cudaFuncAttributeMaxDynamicSharedMemorySize, (int)smem);

    kf_kernel<<<HDIM, 512, smem>>>(kin);
    conv_kernel<<<BDIM * HDIM, 512, smem>>>(u, Dv);
    dim3 grid(LDIM / GBN, HDIM / GBM, BDIM);
    gemm_kernel<<<grid, 256>>>(Wm, bias, outp);
}

// round 2
// speedup vs baseline: 3.1222x; 3.1222x over previous
#include <cuda_runtime.h>
#include <math.h>

// Problem constants
#define MFFT 8192      // complex FFT size (packed real of N=16384)
#define MH   4096      // MFFT/2
#define LOGM 13
#define HDIM 512
#define BDIM 8
#define LDIM 8192

// Device scratch
__device__ float2 g_Kf[HDIM * 8193];                 // rfft(k, 16384) per h, natural order
__device__ float  g_G[(size_t)BDIM * HDIM * LDIM];   // gelu(conv + skip), (B,H,L)

__device__ __forceinline__ float2 cmulf2(float2 a, float2 b) {
    return make_float2(a.x * b.x - a.y * b.y, a.x * b.y + a.y * b.x);
}
__device__ __forceinline__ float2 caddf2(float2 a, float2 b) { return make_float2(a.x + b.x, a.y + b.y); }
__device__ __forceinline__ float2 csubf2(float2 a, float2 b) { return make_float2(a.x - b.x, a.y - b.y); }
__device__ __forceinline__ float2 conjf2(float2 a) { return make_float2(a.x, -a.y); }
__device__ __forceinline__ int rev13(int k) { return (int)(__brev((unsigned)k) >> 19); }

// Fused double radix-2 DIF passes: natural input -> bit-reversed output.
// Identical arithmetic/ordering to 13 single radix-2 DIF stages.
__device__ void fft_forward(float2* A, int tid) {
#pragma unroll
    for (int s = 0; s < 12; s += 2) {
        int ld2 = 11 - s;         // log2(d2); d2 = stride of 2nd stage of the pair
        int d2 = 1 << ld2;
        int d1 = d2 << 1;
        __syncthreads();
#pragma unroll
        for (int p = 0; p < 4; p++) {
            int g = tid + p * 512;
            int tw = g & (d2 - 1);
            int i = ((g >> ld2) << (ld2 + 2)) + tw;
            float2 a0 = A[i], a1 = A[i + d2], a2 = A[i + d1], a3 = A[i + d1 + d2];
            float ang = (-6.283185307179586f / 8192.0f) * (float)(tw << s);
            float sn, cs; __sincosf(ang, &sn, &cs);
            float2 w1 = make_float2(cs, sn);
            float2 w2 = cmulf2(w1, w1);
            float2 s02 = caddf2(a0, a2), d02 = csubf2(a0, a2);
            float2 s13 = caddf2(a1, a3), d13 = csubf2(a1, a3);
            A[i]      = caddf2(s02, s13);
            A[i + d2] = cmulf2(csubf2(s02, s13), w2);
            float2 m  = make_float2(d02.x + d13.y, d02.y - d13.x);   // d02 - i*d13
            A[i + d1] = cmulf2(m, w1);
            float2 pq = make_float2(d02.x - d13.y, d02.y + d13.x);   // d02 + i*d13
            A[i + d1 + d2] = cmulf2(cmulf2(pq, w1), w2);
        }
    }
    // final radix-2 stage, d=1, twiddle = 1
    __syncthreads();
#pragma unroll
    for (int p = 0; p < 8; p++) {
        int j = tid + p * 512;
        float2 a = A[2 * j], b = A[2 * j + 1];
        A[2 * j]     = caddf2(a, b);
        A[2 * j + 1] = csubf2(a, b);
    }
    __syncthreads();
}

// Fused double radix-2 DIT passes (conjugate twiddles): bit-reversed -> natural.
// Unnormalized.
__device__ void fft_inverse(float2* A, int tid) {
    __syncthreads();
#pragma unroll
    for (int p = 0; p < 8; p++) {
        int j = tid + p * 512;
        float2 a = A[2 * j], b = A[2 * j + 1];
        A[2 * j]     = caddf2(a, b);
        A[2 * j + 1] = csubf2(a, b);
    }
#pragma unroll
    for (int s = 1; s < 13; s += 2) {
        int d1 = 1 << s;
        int d2 = d1 << 1;
        __syncthreads();
#pragma unroll
        for (int p = 0; p < 4; p++) {
            int g = tid + p * 512;
            int tw = g & (d1 - 1);
            int i = ((g >> s) << (s + 2)) + tw;
            float2 a0 = A[i], a1 = A[i + d1], a2 = A[i + d2], a3 = A[i + d1 + d2];
            float ang = (6.283185307179586f / 8192.0f) * (float)(tw << (11 - s));
            float sn, cs; __sincosf(ang, &sn, &cs);
            float2 v0 = make_float2(cs, sn);     // conj(W^(t<<(11-s)))
            float2 w  = cmulf2(v0, v0);          // conj(W^(t<<(12-s)))
            float2 t1 = cmulf2(a1, w);
            float2 t3 = cmulf2(a3, w);
            float2 b0 = caddf2(a0, t1), b1 = csubf2(a0, t1);
            float2 b2 = caddf2(a2, t3), b3 = csubf2(a2, t3);
            float2 e  = cmulf2(b2, v0);
            float2 f  = cmulf2(b3, v0);
            A[i]           = caddf2(b0, e);
            A[i + d2]      = csubf2(b0, e);
            A[i + d1]      = make_float2(b1.x - f.y, b1.y + f.x);   // b1 + i*f
            A[i + d1 + d2] = make_float2(b1.x + f.y, b1.y - f.x);   // b1 - i*f
        }
    }
    __syncthreads();
}

// Kernel A: Kf[h] = rfft(k[h], 16384), natural order, 8193 bins.
extern "C" __global__ void __launch_bounds__(512) kf_kernel(const float* __restrict__ kin) {
    extern __shared__ float2 sh[];
    float2* A = sh;
    int tid = threadIdx.x;
    int h = blockIdx.x;
    const float2* kp = (const float2*)(kin + (size_t)h * LDIM);
    for (int j = tid; j < MH; j += 512) {
        A[j] = kp[j];                       // pack: z[j] = x[2j] + i x[2j+1]
        A[j + MH] = make_float2(0.f, 0.f);  // zero padding half
    }
    fft_forward(A, tid);
    float2* outp = g_Kf + (size_t)h * 8193;
    for (int k = tid; k < MH; k += 512) {
        if (k == 0) {
            float2 Z0 = A[0];
            outp[0]    = make_float2(Z0.x + Z0.y, 0.f);
            outp[8192] = make_float2(Z0.x - Z0.y, 0.f);
            outp[4096] = conjf2(A[1]);      // rev13(4096)==1; X[M/2] = conj(Z[M/2])
        } else {
            float2 Zk = A[rev13(k)];
            float2 Zm = A[rev13(MFFT - k)];
            float2 cZm = conjf2(Zm);
            float2 E  = make_float2(0.5f * (Zk.x + cZm.x), 0.5f * (Zk.y + cZm.y));
            float2 Dd = csubf2(Zk, cZm);
            float2 O  = make_float2(0.5f * Dd.y, -0.5f * Dd.x);     // -i*(Zk-conj Zm)/2
            float ang = (-3.14159265358979323846f / 8192.0f) * (float)k;  // W_N^k, N=16384
            float sn, cs; __sincosf(ang, &sn, &cs);
            float2 Wt = make_float2(cs, sn);
            float2 WO = cmulf2(Wt, O);
            outp[k]        = caddf2(E, WO);          // X[k]   = E + W*O
            outp[MFFT - k] = conjf2(csubf2(E, WO));  // X[M-k] = conj(E - W*O)
        }
    }
}

// Kernel B: per (b,h): y = irfft(rfft(u)*Kf)[:L] + D[h]*u ; g = gelu_exact(y) -> g_G
extern "C" __global__ void __launch_bounds__(512) conv_kernel(
    const float* __restrict__ u, const float* __restrict__ Dv) {
    extern __shared__ float2 sh[];
    float2* A = sh;
    int tid = threadIdx.x;
    int b = blockIdx.x & (BDIM - 1);
    int h = blockIdx.x >> 3;   // b fastest -> 8 blocks share Kf[h] in L2 per wave
    const float2* up = (const float2*)(u + ((size_t)b * HDIM + h) * LDIM);
    for (int j = tid; j < MH; j += 512) {
        A[j] = up[j];
        A[j + MH] = make_float2(0.f, 0.f);
    }
    fft_forward(A, tid);

    const float2* Kf = g_Kf + (size_t)h * 8193;
    // unpack -> multiply by Kf -> repack, all in bit-reversed addressing (pairs disjoint)
    for (int k = tid; k < MH; k += 512) {
        if (k == 0) {
            float2 Z0 = A[0];
            float X0 = Z0.x + Z0.y;
            float XM = Z0.x - Z0.y;
            float2 K0 = Kf[0], KM = Kf[8192];
            float2 Y0 = make_float2(X0 * K0.x, X0 * K0.y);
            float2 YM = make_float2(XM * KM.x, XM * KM.y);
            float2 cYM = conjf2(YM);
            float2 Ep = make_float2(0.5f * (Y0.x + cYM.x), 0.5f * (Y0.y + cYM.y));
            float2 Op = make_float2(0.5f * (Y0.x - cYM.x), 0.5f * (Y0.y - cYM.y));
            A[0] = make_float2(Ep.x - Op.y, Ep.y + Op.x);   // Z'[0] = Ep + i*Op
            float2 Zq = A[1];                                // Z[M/2] (bit-rev index 1)
            float2 Yq = cmulf2(conjf2(Zq), Kf[4096]);
            A[1] = conjf2(Yq);                               // Z'[M/2] = conj(Y[M/2])
        } else {
            int rk = rev13(k), rm = rev13(MFFT - k);
            float2 Zk = A[rk], Zm = A[rm];
            float2 cZm = conjf2(Zm);
            float2 E  = make_float2(0.5f * (Zk.x + cZm.x), 0.5f * (Zk.y + cZm.y));
            float2 Dd = csubf2(Zk, cZm);
            float2 O  = make_float2(0.5f * Dd.y, -0.5f * Dd.x);
            float ang = (-3.14159265358979323846f / 8192.0f) * (float)k;
            float sn, cs; __sincosf(ang, &sn, &cs);
            float2 Wt = make_float2(cs, sn);
            float2 WO = cmulf2(Wt, O);
            float2 Xk = caddf2(E, WO);
            float2 Xm = conjf2(csubf2(E, WO));
            float2 Yk = cmulf2(Xk, Kf[k]);
            float2 Ym = cmulf2(Xm, Kf[MFFT - k]);
            float2 cYm = conjf2(Ym);
            float2 Ep = make_float2(0.5f * (Yk.x + cYm.x), 0.5f * (Yk.y + cYm.y));
            float2 P  = make_float2(0.5f * (Yk.x - cYm.x), 0.5f * (Yk.y - cYm.y));
            float2 Op = cmulf2(conjf2(Wt), P);               // O' = W^{-k} * P
            A[rk] = make_float2(Ep.x - Op.y, Ep.y + Op.x);   // Z'[k]   = Ep + i*Op
            A[rm] = make_float2(Ep.x + Op.y, Op.x - Ep.y);   // Z'[M-k] = conj(Ep - i*Op)
        }
    }
    fft_inverse(A, tid);   // leading internal __syncthreads covers the writes above

    float Dh = Dv[h];
    float2* gp = (float2*)(g_G + ((size_t)b * HDIM + h) * LDIM);
    const float inv = 1.0f / (float)MFFT;
    for (int j = tid; j < MH; j += 512) {
        float2 z = A[j];
        float2 uu = up[j];
        float y0 = z.x * inv + Dh * uu.x;
        float y1 = z.y * inv + Dh * uu.y;
        float g0 = 0.5f * y0 * (1.0f + erff(y0 * 0.70710678118654752440f));
        float g1 = 0.5f * y1 * (1.0f + erff(y1 * 0.70710678118654752440f));
        gp[j] = make_float2(g0, g1);
    }
}

// Kernel C: out[b,o,l] = sum_h W[o,h] * g_G[b,h,l] + bias[o]
// 128x128 tile, GBK=16, double-buffered smem, 256 threads, 8x8 microtile (4+4 split).
#define GBM 128
#define GBN 128
#define GBK 16
extern "C" __global__ void __launch_bounds__(256) gemm_kernel(
    const float* __restrict__ Wm, const float* __restrict__ bias, float* __restrict__ outp) {
    __shared__ float As[2][GBK][GBM + 4];   // As[k][m], row stride 132 (16B aligned)
    __shared__ float Bs[2][GBK][GBN];       // Bs[k][n]
    int t = threadIdx.x;
    int b = blockIdx.z;
    int o0 = blockIdx.x * GBM;   // o-tile fastest for g L2 reuse
    int l0 = blockIdx.y * GBN;
    int tx = t & 15, ty = t >> 4;

    // W loads: row wo, 8 consecutive k at wk
    int wo = t >> 1, wk = (t & 1) * 8;
    // G loads: k-row gk, cols gl and gl+64 (4 floats each)
    int gk = t >> 4, gl = (t & 15) * 4;

    const float* wp = Wm + (size_t)(o0 + wo) * HDIM + wk;
    const float* gp = g_G + (size_t)b * HDIM * LDIM + (size_t)gk * LDIM + l0 + gl;

    float4 wr0, wr1, gr0, gr1;
    wr0 = *(const float4*)(wp);
    wr1 = *(const float4*)(wp + 4);
    gr0 = *(const float4*)(gp);
    gr1 = *(const float4*)(gp + 64);
    {
        float tmp[8] = {wr0.x, wr0.y, wr0.z, wr0.w, wr1.x, wr1.y, wr1.z, wr1.w};
#pragma unroll
        for (int j = 0; j < 8; j++) As[0][wk + j][wo] = tmp[j];
        *(float4*)&Bs[0][gk][gl]      = gr0;
        *(float4*)&Bs[0][gk][gl + 64] = gr1;
    }
    __syncthreads();

    float acc[8][8];
#pragma unroll
    for (int i = 0; i < 8; i++)
#pragma unroll
        for (int j = 0; j < 8; j++) acc[i][j] = 0.f;

    int cur = 0;
    for (int k0 = GBK; k0 <= HDIM; k0 += GBK) {
        bool more = (k0 < HDIM);
        if (more) {
            wr0 = *(const float4*)(wp + k0);
            wr1 = *(const float4*)(wp + k0 + 4);
            gr0 = *(const float4*)(gp + (size_t)k0 * LDIM);
            gr1 = *(const float4*)(gp + (size_t)k0 * LDIM + 64);
        }
#pragma unroll
        for (int kk = 0; kk < GBK; kk++) {
            float4 a0 = *(const float4*)&As[cur][kk][ty * 4];
            float4 a1 = *(const float4*)&As[cur][kk][ty * 4 + 64];
            float4 b0 = *(const float4*)&Bs[cur][kk][tx * 4];
            float4 b1 = *(const float4*)&Bs[cur][kk][tx * 4 + 64];
            float av[8] = {a0.x, a0.y, a0.z, a0.w, a1.x, a1.y, a1.z, a1.w};
            float bv[8] = {b0.x, b0.y, b0.z, b0.w, b1.x, b1.y, b1.z, b1.w};
#pragma unroll
            for (int i = 0; i < 8; i++)
#pragma unroll
                for (int j = 0; j < 8; j++) acc[i][j] = fmaf(av[i], bv[j], acc[i][j]);
        }
        if (more) {
            float tmp[8] = {wr0.x, wr0.y, wr0.z, wr0.w, wr1.x, wr1.y, wr1.z, wr1.w};
#pragma unroll
            for (int j = 0; j < 8; j++) As[cur ^ 1][wk + j][wo] = tmp[j];
            *(float4*)&Bs[cur ^ 1][gk][gl]      = gr0;
            *(float4*)&Bs[cur ^ 1][gk][gl + 64] = gr1;
        }
        __syncthreads();
        cur ^= 1;
    }

#pragma unroll
    for (int i = 0; i < 8; i++) {
        int row = o0 + ty * 4 + ((i < 4) ? i : (64 + i - 4));
        float bs = bias[row];
        float4 v0 = make_float4(acc[i][0] + bs, acc[i][1] + bs, acc[i][2] + bs, acc[i][3] + bs);
        float4 v1 = make_float4(acc[i][4] + bs, acc[i][5] + bs, acc[i][6] + bs, acc[i][7] + bs);
        float* op = outp + ((size_t)b * HDIM + row) * LDIM + l0 + tx * 4;
        *(float4*)(op)      = v0;
        *(float4*)(op + 64) = v1;
    }
}

extern "C" void kernel_launch(void* const* d_in, const int* in_sizes, int n_in,
                              void* d_out, int out_size) {
    const float* u    = (const float*)d_in[0];   // (8,512,8192)
    const float* kin  = (const float*)d_in[1];   // (1,512,8192)
    const float* Dv   = (const float*)d_in[2];   // (1,512)
    const float* Wm   = (const float*)d_in[3];   // (512,512)
    const float* bias = (const float*)d_in[4];   // (512,)
    float* outp = (float*)d_out;                 // (8,512,8192)

    size_t smem = (size_t)MFFT * sizeof(float2);  // 64 KB (no twiddle table)
    cudaFuncSetAttribute(kf_kernel,   cudaFuncAttributeMaxDynamicSharedMemorySize, (int)smem);
    cudaFuncSetAttribute(conv_kernel, cudaFuncAttributeMaxDynamicSharedMemorySize, (int)smem);

    kf_kernel<<<HDIM, 512, smem>>>(kin);
    conv_kernel<<<BDIM * HDIM, 512, smem>>>(u, Dv);
    dim3 grid(HDIM / GBM, LDIM / GBN, BDIM);
    gemm_kernel<<<grid, 256>>>(Wm, bias, outp);
}

// round 6
// speedup vs baseline: 4.2145x; 1.3499x over previous
#include <cuda_runtime.h>
#include <cuda_fp16.h>
#include <math.h>
#include <stdint.h>

// Problem constants
#define MFFT 8192      // complex FFT size (packed real of N=16384)
#define MH   4096      // MFFT/2
#define LOGM 13
#define HDIM 512
#define BDIM 8
#define LDIM 8192

// Device scratch
__device__ float2   g_Kf[HDIM * 8193];                  // rfft(k, 16384) per h
__device__ uint32_t g_P[(size_t)BDIM * HDIM * LDIM];    // gelu result, fp16 (h, h) duplicated
__device__ uint32_t g_Wp[HDIM * HDIM];                  // W fp16 (hi, lo) split

__device__ __forceinline__ float2 cmulf2(float2 a, float2 b) {
    return make_float2(a.x * b.x - a.y * b.y, a.x * b.y + a.y * b.x);
}
__device__ __forceinline__ float2 caddf2(float2 a, float2 b) { return make_float2(a.x + b.x, a.y + b.y); }
__device__ __forceinline__ float2 csubf2(float2 a, float2 b) { return make_float2(a.x - b.x, a.y - b.y); }
__device__ __forceinline__ float2 conjf2(float2 a) { return make_float2(a.x, -a.y); }
__device__ __forceinline__ int rev13(int k) { return (int)(__brev((unsigned)k) >> 19); }

// W side: (hi, lo) fp16 split -> hi+lo represents W to ~2^-21
__device__ __forceinline__ uint32_t pack_w(float v) {
    __half h = __float2half_rn(v);
    __half l = __float2half_rn(v - __half2float(h));
    return (uint32_t)__half_as_ushort(h) | ((uint32_t)__half_as_ushort(l) << 16);
}
// g side: (h, h) duplicated fp16 -> pairs with (hi, lo) to give (hi+lo)*h
__device__ __forceinline__ uint32_t pack_g(float v) {
    uint32_t h = (uint32_t)__half_as_ushort(__float2half_rn(v));
    return h | (h << 16);
}

// ---------------- FFT machinery (unchanged) ----------------
__device__ void fft_forward(float2* A, int tid) {
#pragma unroll
    for (int s = 0; s < 12; s += 2) {
        int ld2 = 11 - s;
        int d2 = 1 << ld2;
        int d1 = d2 << 1;
        __syncthreads();
#pragma unroll
        for (int p = 0; p < 4; p++) {
            int g = tid + p * 512;
            int tw = g & (d2 - 1);
            int i = ((g >> ld2) << (ld2 + 2)) + tw;
            float2 a0 = A[i], a1 = A[i + d2], a2 = A[i + d1], a3 = A[i + d1 + d2];
            float ang = (-6.283185307179586f / 8192.0f) * (float)(tw << s);
            float sn, cs; __sincosf(ang, &sn, &cs);
            float2 w1 = make_float2(cs, sn);
            float2 w2 = cmulf2(w1, w1);
            float2 s02 = caddf2(a0, a2), d02 = csubf2(a0, a2);
            float2 s13 = caddf2(a1, a3), d13 = csubf2(a1, a3);
            A[i]      = caddf2(s02, s13);
            A[i + d2] = cmulf2(csubf2(s02, s13), w2);
            float2 m  = make_float2(d02.x + d13.y, d02.y - d13.x);
            A[i + d1] = cmulf2(m, w1);
            float2 pq = make_float2(d02.x - d13.y, d02.y + d13.x);
            A[i + d1 + d2] = cmulf2(cmulf2(pq, w1), w2);
        }
    }
    __syncthreads();
#pragma unroll
    for (int p = 0; p < 8; p++) {
        int j = tid + p * 512;
        float2 a = A[2 * j], b = A[2 * j + 1];
        A[2 * j]     = caddf2(a, b);
        A[2 * j + 1] = csubf2(a, b);
    }
    __syncthreads();
}

__device__ void fft_inverse(float2* A, int tid) {
    __syncthreads();
#pragma unroll
    for (int p = 0; p < 8; p++) {
        int j = tid + p * 512;
        float2 a = A[2 * j], b = A[2 * j + 1];
        A[2 * j]     = caddf2(a, b);
        A[2 * j + 1] = csubf2(a, b);
    }
#pragma unroll
    for (int s = 1; s < 13; s += 2) {
        int d1 = 1 << s;
        int d2 = d1 << 1;
        __syncthreads();
#pragma unroll
        for (int p = 0; p < 4; p++) {
            int g = tid + p * 512;
            int tw = g & (d1 - 1);
            int i = ((g >> s) << (s + 2)) + tw;
            float2 a0 = A[i], a1 = A[i + d1], a2 = A[i + d2], a3 = A[i + d1 + d2];
            float ang = (6.283185307179586f / 8192.0f) * (float)(tw << (11 - s));
            float sn, cs; __sincosf(ang, &sn, &cs);
            float2 v0 = make_float2(cs, sn);
            float2 w  = cmulf2(v0, v0);
            float2 t1 = cmulf2(a1, w);
            float2 t3 = cmulf2(a3, w);
            float2 b0 = caddf2(a0, t1), b1 = csubf2(a0, t1);
            float2 b2 = caddf2(a2, t3), b3 = csubf2(a2, t3);
            float2 e  = cmulf2(b2, v0);
            float2 f  = cmulf2(b3, v0);
            A[i]           = caddf2(b0, e);
            A[i + d2]      = csubf2(b0, e);
            A[i + d1]      = make_float2(b1.x - f.y, b1.y + f.x);
            A[i + d1 + d2] = make_float2(b1.x + f.y, b1.y - f.x);
        }
    }
    __syncthreads();
}

// Kernel A: Kf[h] = rfft(k[h], 16384)
extern "C" __global__ void __launch_bounds__(512) kf_kernel(const float* __restrict__ kin) {
    extern __shared__ float2 sh[];
    float2* A = sh;
    int tid = threadIdx.x;
    int h = blockIdx.x;
    const float2* kp = (const float2*)(kin + (size_t)h * LDIM);
    for (int j = tid; j < MH; j += 512) {
        A[j] = kp[j];
        A[j + MH] = make_float2(0.f, 0.f);
    }
    fft_forward(A, tid);
    float2* outp = g_Kf + (size_t)h * 8193;
    for (int k = tid; k < MH; k += 512) {
        if (k == 0) {
            float2 Z0 = A[0];
            outp[0]    = make_float2(Z0.x + Z0.y, 0.f);
            outp[8192] = make_float2(Z0.x - Z0.y, 0.f);
            outp[4096] = conjf2(A[1]);
        } else {
            float2 Zk = A[rev13(k)];
            float2 Zm = A[rev13(MFFT - k)];
            float2 cZm = conjf2(Zm);
            float2 E  = make_float2(0.5f * (Zk.x + cZm.x), 0.5f * (Zk.y + cZm.y));
            float2 Dd = csubf2(Zk, cZm);
            float2 O  = make_float2(0.5f * Dd.y, -0.5f * Dd.x);
            float ang = (-3.14159265358979323846f / 8192.0f) * (float)k;
            float sn, cs; __sincosf(ang, &sn, &cs);
            float2 Wt = make_float2(cs, sn);
            float2 WO = cmulf2(Wt, O);
            outp[k]        = caddf2(E, WO);
            outp[MFFT - k] = conjf2(csubf2(E, WO));
        }
    }
}

// Kernel B: conv + skip + gelu -> fp16 (h,h) words
extern "C" __global__ void __launch_bounds__(512) conv_kernel(
    const float* __restrict__ u, const float* __restrict__ Dv) {
    extern __shared__ float2 sh[];
    float2* A = sh;
    int tid = threadIdx.x;
    int b = blockIdx.x & (BDIM - 1);
    int h = blockIdx.x >> 3;
    const float2* up = (const float2*)(u + ((size_t)b * HDIM + h) * LDIM);
    for (int j = tid; j < MH; j += 512) {
        A[j] = up[j];
        A[j + MH] = make_float2(0.f, 0.f);
    }
    fft_forward(A, tid);

    const float2* Kf = g_Kf + (size_t)h * 8193;
    for (int k = tid; k < MH; k += 512) {
        if (k == 0) {
            float2 Z0 = A[0];
            float X0 = Z0.x + Z0.y;
            float XM = Z0.x - Z0.y;
            float2 K0 = Kf[0], KM = Kf[8192];
            float2 Y0 = make_float2(X0 * K0.x, X0 * K0.y);
            float2 YM = make_float2(XM * KM.x, XM * KM.y);
            float2 cYM = conjf2(YM);
            float2 Ep = make_float2(0.5f * (Y0.x + cYM.x), 0.5f * (Y0.y + cYM.y));
            float2 Op = make_float2(0.5f * (Y0.x - cYM.x), 0.5f * (Y0.y - cYM.y));
            A[0] = make_float2(Ep.x - Op.y, Ep.y + Op.x);
            float2 Zq = A[1];
            float2 Yq = cmulf2(conjf2(Zq), Kf[4096]);
            A[1] = conjf2(Yq);
        } else {
            int rk = rev13(k), rm = rev13(MFFT - k);
            float2 Zk = A[rk], Zm = A[rm];
            float2 cZm = conjf2(Zm);
            float2 E  = make_float2(0.5f * (Zk.x + cZm.x), 0.5f * (Zk.y + cZm.y));
            float2 Dd = csubf2(Zk, cZm);
            float2 O  = make_float2(0.5f * Dd.y, -0.5f * Dd.x);
            float ang = (-3.14159265358979323846f / 8192.0f) * (float)k;
            float sn, cs; __sincosf(ang, &sn, &cs);
            float2 Wt = make_float2(cs, sn);
            float2 WO = cmulf2(Wt, O);
            float2 Xk = caddf2(E, WO);
            float2 Xm = conjf2(csubf2(E, WO));
            float2 Yk = cmulf2(Xk, Kf[k]);
            float2 Ym = cmulf2(Xm, Kf[MFFT - k]);
            float2 cYm = conjf2(Ym);
            float2 Ep = make_float2(0.5f * (Yk.x + cYm.x), 0.5f * (Yk.y + cYm.y));
            float2 P  = make_float2(0.5f * (Yk.x - cYm.x), 0.5f * (Yk.y - cYm.y));
            float2 Op = cmulf2(conjf2(Wt), P);
            A[rk] = make_float2(Ep.x - Op.y, Ep.y + Op.x);
            A[rm] = make_float2(Ep.x + Op.y, Op.x - Ep.y);
        }
    }
    fft_inverse(A, tid);

    float Dh = Dv[h];
    uint2* gp = (uint2*)(g_P + ((size_t)b * HDIM + h) * LDIM);
    const float inv = 1.0f / (float)MFFT;
    for (int j = tid; j < MH; j += 512) {
        float2 z = A[j];
        float2 uu = up[j];
        float y0 = z.x * inv + Dh * uu.x;
        float y1 = z.y * inv + Dh * uu.y;
        float g0 = 0.5f * y0 * (1.0f + erff(y0 * 0.70710678118654752440f));
        float g1 = 0.5f * y1 * (1.0f + erff(y1 * 0.70710678118654752440f));
        gp[j] = make_uint2(pack_g(g0), pack_g(g1));
    }
}

// W pack kernel
extern "C" __global__ void __launch_bounds__(256) wpack_kernel(const float* __restrict__ Wm) {
    int i = blockIdx.x * 256 + threadIdx.x;
    g_Wp[i] = pack_w(Wm[i]);
}

// ---------------- mma.sync GEMM ----------------
__device__ __forceinline__ uint32_t smem_u32(const void* p) {
    return (uint32_t)__cvta_generic_to_shared(p);
}
__device__ __forceinline__ uint32_t swz(uint32_t off) { return off ^ ((off >> 3) & 0x70); }

__device__ __forceinline__ void ldmat4(uint32_t* r, uint32_t addr) {
    asm volatile("ldmatrix.sync.aligned.m8n8.x4.shared.b16 {%0,%1,%2,%3}, [%4];"
                 : "=r"(r[0]), "=r"(r[1]), "=r"(r[2]), "=r"(r[3]) : "r"(addr));
}
__device__ __forceinline__ void mma16816(float* d, const uint32_t* a, uint32_t b0, uint32_t b1) {
    asm volatile(
        "mma.sync.aligned.m16n8k16.row.col.f32.f16.f16.f32 "
        "{%0,%1,%2,%3}, {%4,%5,%6,%7}, {%8,%9}, {%0,%1,%2,%3};"
        : "+f"(d[0]), "+f"(d[1]), "+f"(d[2]), "+f"(d[3])
        : "r"(a[0]), "r"(a[1]), "r"(a[2]), "r"(a[3]), "r"(b0), "r"(b1));
}
#define CP16(dst, src) asm volatile("cp.async.cg.shared.global [%0], [%1], 16;" :: "r"(dst), "l"(src) : "memory")
#define CP4(dst, src)  asm volatile("cp.async.ca.shared.global [%0], [%1], 4;"  :: "r"(dst), "l"(src) : "memory")
#define CP_COMMIT()    asm volatile("cp.async.commit_group;" ::: "memory")
#define CP_WAIT1()     asm volatile("cp.async.wait_group 1;" ::: "memory")

// Tiles: 128(o) x 128(l), K'=1024 fp16 in 16 chunks of 64 (=32 packed words).
// smem: A0 @0, A1 @16K, B0 @32K, B1 @48K. Rows are 128B, XOR-swizzled in 16B units.
// Pipeline: prologue loads chunk 0; iter c loads chunk c+1 into the OTHER
// buffer, then computes chunk c. Trailing barrier protects buffer reuse.
extern "C" __global__ void __launch_bounds__(256) gemm_mma_kernel(
    const float* __restrict__ bias, float* __restrict__ outp) {
    extern __shared__ char smem[];
    uint32_t sb = smem_u32(smem);
    int t = threadIdx.x;
    int lane = t & 31, wid = t >> 5;
    int warp_m = wid >> 2, warp_n = wid & 3;   // 2 x 4 warp grid; warp tile 64x32
    int o0 = blockIdx.x * 128, l0 = blockIdx.y * 128, b = blockIdx.z;

    // A load indexing: thread t -> row t>>1, k-word half (t&1)*16, 4 x 16B cp.async
    int a_row = t >> 1, a_half = t & 1;
    const uint32_t* wp = g_Wp + (size_t)(o0 + a_row) * HDIM + a_half * 16;
    // B load indexing: thread t -> l = t&127, h-word group (t>>7)*16, 16 x 4B cp.async
    int b_l = t & 127, b_hg = (t >> 7) * 16;
    const uint32_t* gpB = g_P + (size_t)b * HDIM * LDIM + l0 + b_l;

    auto load_chunk = [&](int c) {
        int buf = c & 1;
        uint32_t sA = sb + buf * 16384;
        uint32_t sB = sb + 32768 + buf * 16384;
        const uint32_t* aw = wp + c * 32;
#pragma unroll
        for (int j = 0; j < 4; j++) {
            uint32_t off = (uint32_t)(a_row * 128 + (a_half * 16 + j * 4) * 4);
            CP16(sA + swz(off), aw + j * 4);
        }
#pragma unroll
        for (int q = 0; q < 16; q++) {
            int hw = b_hg + q;
            uint32_t off = (uint32_t)(b_l * 128 + hw * 4);
            CP4(sB + swz(off), gpB + (size_t)(c * 32 + hw) * LDIM);
        }
    };

    // ldmatrix per-lane addressing (within a 16x16 tile, rows stride 128B):
    int a_lrow = (lane & 7) + ((lane >> 3) & 1) * 8;
    int a_lcol = (lane >> 4) * 16;
    int b_lrow = (lane & 7) + ((lane >> 4) & 1) * 8;
    int b_lcol = ((lane >> 3) & 1) * 16;
    uint32_t xorm = (uint32_t)((lane & 7) << 4);

    float acc[4][4][4];
#pragma unroll
    for (int i = 0; i < 4; i++)
#pragma unroll
        for (int j = 0; j < 4; j++)
#pragma unroll
            for (int q = 0; q < 4; q++) acc[i][j][q] = 0.f;

    load_chunk(0);
    CP_COMMIT();

#pragma unroll 1
    for (int c = 0; c < 16; c++) {
        if (c + 1 < 16) load_chunk(c + 1);   // other buffer than compute below
        CP_COMMIT();
        CP_WAIT1();          // chunk c's group complete (newest group still in flight)
        __syncthreads();     // make all threads' cp.async data visible
        int buf = c & 1;
        uint32_t sA = sb + buf * 16384;
        uint32_t sB = sb + 32768 + buf * 16384;
#pragma unroll
        for (int s = 0; s < 4; s++) {
            uint32_t afr[4][4];
#pragma unroll
            for (int mt = 0; mt < 4; mt++) {
                uint32_t off = (uint32_t)((warp_m * 64 + mt * 16 + a_lrow) * 128 + s * 32 + a_lcol);
                ldmat4(afr[mt], sA + (off ^ xorm));
            }
#pragma unroll
            for (int bt = 0; bt < 2; bt++) {
                uint32_t bfr[4];
                uint32_t off = (uint32_t)((warp_n * 32 + bt * 16 + b_lrow) * 128 + s * 32 + b_lcol);
                ldmat4(bfr, sB + (off ^ xorm));
#pragma unroll
                for (int mt = 0; mt < 4; mt++) {
                    mma16816(acc[mt][bt * 2 + 0], afr[mt], bfr[0], bfr[1]);
                    mma16816(acc[mt][bt * 2 + 1], afr[mt], bfr[2], bfr[3]);
                }
            }
        }
        __syncthreads();     // buffer c&1 free before iter c+1 loads chunk c+2 into it
    }

    // Epilogue: acc[mt][nt]: rows r, r+8; cols nt*8 + (lane&3)*2
#pragma unroll
    for (int mt = 0; mt < 4; mt++) {
        int r = o0 + warp_m * 64 + mt * 16 + (lane >> 2);
        float bs0 = bias[r], bs1 = bias[r + 8];
        float* p0 = outp + ((size_t)b * HDIM + r) * LDIM + l0 + warp_n * 32 + (lane & 3) * 2;
        float* p1 = p0 + 8 * LDIM;
#pragma unroll
        for (int nt = 0; nt < 4; nt++) {
            float2 v0 = make_float2(acc[mt][nt][0] + bs0, acc[mt][nt][1] + bs0);
            float2 v1 = make_float2(acc[mt][nt][2] + bs1, acc[mt][nt][3] + bs1);
            *(float2*)(p0 + nt * 8) = v0;
            *(float2*)(p1 + nt * 8) = v1;
        }
    }
}

extern "C" void kernel_launch(void* const* d_in, const int* in_sizes, int n_in,
                              void* d_out, int out_size) {
    const float* u    = (const float*)d_in[0];   // (8,512,8192)
    const float* kin  = (const float*)d_in[1];   // (1,512,8192)
    const float* Dv   = (const float*)d_in[2];   // (1,512)
    const float* Wm   = (const float*)d_in[3];   // (512,512)
    const float* bias = (const float*)d_in[4];   // (512,)
    float* outp = (float*)d_out;                 // (8,512,8192)

    size_t smem = (size_t)MFFT * sizeof(float2);  // 64 KB
    cudaFuncSetAttribute(kf_kernel,   cudaFuncAttributeMaxDynamicSharedMemorySize, (int)smem);
    cudaFuncSetAttribute(conv_kernel, cudaFuncAttributeMaxDynamicSharedMemorySize, (int)smem);
    size_t gsmem = 65536;                          // A0,A1,B0,B1 x 16KB
    cudaFuncSetAttribute(gemm_mma_kernel, cudaFuncAttributeMaxDynamicSharedMemorySize, (int)gsmem);

    wpack_kernel<<<HDIM * HDIM / 256, 256>>>(Wm);
    kf_kernel<<<HDIM, 512, smem>>>(kin);
    conv_kernel<<<BDIM * HDIM, 512, smem>>>(u, Dv);
    dim3 grid(HDIM / 128, LDIM / 128, BDIM);      // o fastest -> B-panel L2 reuse
    gemm_mma_kernel<<<grid, 256, gsmem>>>(bias, outp);
}